// round 1
// baseline (speedup 1.0000x reference)
#include <cuda_runtime.h>
#include <math.h>

#define N_NODES 50000
#define N_EDGES 800000

// Scratch (device globals — allocation-free per harness rules)
__device__ int   g_degi[N_NODES];
__device__ float g_dinv[N_NODES];
__device__ float g_t[N_NODES * 64];     // t = x @ W1
__device__ float g_agg[N_NODES * 64];   // normalized aggregation
__device__ float g_P[N_NODES * 128];    // [A | B] per-node precompute for edge MLP

__global__ void k_init_deg() {
    int i = blockIdx.x * blockDim.x + threadIdx.x;
    if (i < N_NODES) g_degi[i] = 1;  // self loop
}

__global__ void k_count(const int* __restrict__ dst) {
    int e = blockIdx.x * blockDim.x + threadIdx.x;
    if (e < N_EDGES) atomicAdd(&g_degi[dst[e]], 1);
}

__global__ void k_dinv() {
    int i = blockIdx.x * blockDim.x + threadIdx.x;
    if (i < N_NODES) g_dinv[i] = rsqrtf((float)g_degi[i]);
}

// t = x @ W1 ; agg = t * dinv^2 (self-loop contribution, also initializes agg)
// block = 256 threads = 16 rows x 16 col-groups(x4)
__global__ void k_mm1(const float* __restrict__ x, const float* __restrict__ W1) {
    __shared__ float sW[64 * 64];
    __shared__ float sx[16 * 64];
    int tid = threadIdx.x;
    for (int i = tid; i < 4096; i += 256) sW[i] = W1[i];
    int row0 = blockIdx.x * 16;
    for (int i = tid; i < 1024; i += 256) {
        int r = i >> 6, k = i & 63;
        int row = row0 + r;
        sx[i] = (row < N_NODES) ? x[row * 64 + k] : 0.f;
    }
    __syncthreads();
    int r = tid >> 4, jg = tid & 15;
    int row = row0 + r;
    if (row >= N_NODES) return;
    float4 acc = make_float4(0.f, 0.f, 0.f, 0.f);
    const float4* sW4 = (const float4*)sW;
#pragma unroll
    for (int k = 0; k < 64; k++) {
        float xv = sx[r * 64 + k];
        float4 w = sW4[k * 16 + jg];
        acc.x += xv * w.x; acc.y += xv * w.y; acc.z += xv * w.z; acc.w += xv * w.w;
    }
    float di = g_dinv[row];
    float w2 = di * di;
    ((float4*)g_t)[row * 16 + jg] = acc;
    float4 av = make_float4(acc.x * w2, acc.y * w2, acc.z * w2, acc.w * w2);
    ((float4*)g_agg)[row * 16 + jg] = av;
}

// agg[dst] += t[src] * dinv[src]*dinv[dst]   (16 threads per edge, float4 atomics)
__global__ void k_scatter(const int* __restrict__ src, const int* __restrict__ dst) {
    unsigned int gid = blockIdx.x * blockDim.x + threadIdx.x;
    unsigned int e = gid >> 4;
    int c = gid & 15;
    if (e >= N_EDGES) return;
    int s = src[e], d = dst[e];
    float w = g_dinv[s] * g_dinv[d];
    float4 v = ((const float4*)g_t)[s * 16 + c];
    float4 m = make_float4(v.x * w, v.y * w, v.z * w, v.w * w);
    atomicAdd(((float4*)g_agg) + (d * 16 + c), m);
}

// h = relu(agg + b1); P[:,0:64] = h@Wm1[0:64] + bm1; P[:,64:128] = h@Wm1[64:128]
// block = 256 threads = 8 rows x 32 col-groups(x4 over 128 cols)
__global__ void k_mm2(const float* __restrict__ Wm1, const float* __restrict__ b1,
                      const float* __restrict__ bm1) {
    __shared__ float sW[64 * 128];  // interleaved [k][0:64]=Wm1[k], [k][64:128]=Wm1[64+k]
    __shared__ float sh[8 * 64];
    int tid = threadIdx.x;
    for (int i = tid; i < 4096; i += 256) {
        int k = i >> 6, j = i & 63;
        sW[k * 128 + j]      = Wm1[k * 64 + j];
        sW[k * 128 + 64 + j] = Wm1[(64 + k) * 64 + j];
    }
    int row0 = blockIdx.x * 8;
    for (int i = tid; i < 512; i += 256) {
        int r = i >> 6, k = i & 63;
        int row = row0 + r;
        sh[i] = (row < N_NODES) ? fmaxf(g_agg[row * 64 + k] + b1[k], 0.f) : 0.f;
    }
    __syncthreads();
    int r = tid >> 5, jg = tid & 31;
    int row = row0 + r;
    if (row >= N_NODES) return;
    float4 acc = make_float4(0.f, 0.f, 0.f, 0.f);
    const float4* sW4 = (const float4*)sW;
#pragma unroll
    for (int k = 0; k < 64; k++) {
        float hv = sh[r * 64 + k];
        float4 w = sW4[k * 32 + jg];
        acc.x += hv * w.x; acc.y += hv * w.y; acc.z += hv * w.z; acc.w += hv * w.w;
    }
    if (jg < 16) {  // fold bm1 into the A half (added exactly once per edge)
        float4 b = ((const float4*)bm1)[jg];
        acc.x += b.x; acc.y += b.y; acc.z += b.z; acc.w += b.w;
    }
    ((float4*)g_P)[row * 32 + jg] = acc;
}

// per-edge: hidden = relu(A[src] + B[dst] + ea@We); out = sigmoid(hidden . Wm2 + bm2)
__global__ void k_edge(const int* __restrict__ src, const int* __restrict__ dst,
                       const float* __restrict__ ea, const float* __restrict__ Wm1,
                       const float* __restrict__ Wm2, const float* __restrict__ bm2,
                       float* __restrict__ out) {
    __shared__ float4 sWe[16 * 16];  // Wm1 rows 128..143 as [k][jg]
    __shared__ float sW2[64];
    __shared__ float sb2;
    int tid = threadIdx.x;
    {
        int k = tid >> 4, jg = tid & 15;
        sWe[tid] = ((const float4*)(Wm1 + (128 + k) * 64))[jg];
    }
    if (tid < 64) sW2[tid] = Wm2[tid];
    if (tid == 0) sb2 = bm2[0];
    __syncthreads();
    unsigned int e = blockIdx.x * blockDim.x + tid;
    if (e >= N_EDGES) return;
    int s = src[e], d = dst[e];
    const float4* Ps = (const float4*)(g_P + s * 128);
    const float4* Pd = (const float4*)(g_P + d * 128 + 64);
    float eav[16];
    const float4* ea4 = (const float4*)(ea + (size_t)e * 16);
#pragma unroll
    for (int q = 0; q < 4; q++) {
        float4 v = ea4[q];
        eav[4 * q] = v.x; eav[4 * q + 1] = v.y; eav[4 * q + 2] = v.z; eav[4 * q + 3] = v.w;
    }
    float acc = 0.f;
#pragma unroll
    for (int jg = 0; jg < 16; jg++) {
        float4 a = Ps[jg];
        float4 b = Pd[jg];
        float4 v = make_float4(a.x + b.x, a.y + b.y, a.z + b.z, a.w + b.w);
#pragma unroll
        for (int k = 0; k < 16; k++) {
            float ek = eav[k];
            float4 w = sWe[k * 16 + jg];
            v.x += ek * w.x; v.y += ek * w.y; v.z += ek * w.z; v.w += ek * w.w;
        }
        v.x = fmaxf(v.x, 0.f); v.y = fmaxf(v.y, 0.f);
        v.z = fmaxf(v.z, 0.f); v.w = fmaxf(v.w, 0.f);
        acc += v.x * sW2[4 * jg] + v.y * sW2[4 * jg + 1]
             + v.z * sW2[4 * jg + 2] + v.w * sW2[4 * jg + 3];
    }
    out[e] = 1.f / (1.f + __expf(-(acc + sb2)));
}

extern "C" void kernel_launch(void* const* d_in, const int* in_sizes, int n_in,
                              void* d_out, int out_size) {
    const float* x   = (const float*)d_in[0];
    const int*   src = (const int*)d_in[1];
    const int*   dst = (const int*)d_in[2];
    const float* ea  = (const float*)d_in[3];
    const float* W1  = (const float*)d_in[4];
    // b1 = d_in[5]
    const float* b1  = (const float*)d_in[5];
    const float* Wm1 = (const float*)d_in[6];
    const float* bm1 = (const float*)d_in[7];
    const float* Wm2 = (const float*)d_in[8];
    const float* bm2 = (const float*)d_in[9];
    float* out = (float*)d_out;
    (void)in_sizes; (void)n_in; (void)out_size;

    k_init_deg<<<(N_NODES + 255) / 256, 256>>>();
    k_count<<<(N_EDGES + 255) / 256, 256>>>(dst);
    k_dinv<<<(N_NODES + 255) / 256, 256>>>();
    k_mm1<<<(N_NODES + 15) / 16, 256>>>(x, W1);
    k_scatter<<<(N_EDGES * 16 + 255) / 256, 256>>>(src, dst);
    k_mm2<<<(N_NODES + 7) / 8, 256>>>(Wm1, b1, bm1);
    k_edge<<<(N_EDGES + 255) / 256, 256>>>(src, dst, ea, Wm1, Wm2, bm2, out);
}

// round 2
// speedup vs baseline: 1.1328x; 1.1328x over previous
#include <cuda_runtime.h>
#include <math.h>

#define N_NODES 50000
#define N_EDGES 800000

// Scratch (device globals — allocation-free per harness rules)
__device__ int   g_degi[N_NODES];
__device__ int   g_off[N_NODES];
__device__ int   g_cursor[N_NODES];
__device__ int   g_bsum[64];
__device__ int   g_eid[N_EDGES];
__device__ float g_dinv[N_NODES];
__device__ float g_t[N_NODES * 64];     // t = x @ W1
__device__ float g_agg[N_NODES * 64];   // normalized aggregation
__device__ float g_P[N_NODES * 128];    // [A | B] per-node precompute for edge MLP

__global__ void k_zero() {
    int i = blockIdx.x * blockDim.x + threadIdx.x;
    if (i < N_NODES) g_degi[i] = 0;
}

__global__ void k_count(const int* __restrict__ dst) {
    int e = blockIdx.x * blockDim.x + threadIdx.x;
    if (e < N_EDGES) atomicAdd(&g_degi[dst[e]], 1);
}

// ---- exclusive prefix scan over g_degi (50000) → g_off ----
// scan1: per-block (1024) exclusive scan, block totals to g_bsum
__global__ void k_scan1() {
    int tid = threadIdx.x;
    int i = blockIdx.x * 1024 + tid;
    int v = (i < N_NODES) ? g_degi[i] : 0;
    int lane = tid & 31, wid = tid >> 5;
    int s = v;
#pragma unroll
    for (int o = 1; o < 32; o <<= 1) {
        int t = __shfl_up_sync(0xffffffffu, s, o);
        if (lane >= o) s += t;
    }
    __shared__ int ws[32];
    if (lane == 31) ws[wid] = s;
    __syncthreads();
    if (wid == 0) {
        int t = ws[lane];
        int ss = t;
#pragma unroll
        for (int o = 1; o < 32; o <<= 1) {
            int u = __shfl_up_sync(0xffffffffu, ss, o);
            if (lane >= o) ss += u;
        }
        ws[lane] = ss - t;  // exclusive warp offsets
    }
    __syncthreads();
    int excl = ws[wid] + s - v;
    if (i < N_NODES) g_off[i] = excl;
    if (tid == 1023) g_bsum[blockIdx.x] = ws[31] + s;  // block total
}

// scan2: exclusive scan of up-to-64 block sums (single block of 64)
__global__ void k_scan2(int nb) {
    __shared__ int a[64];
    int t = threadIdx.x;
    int v = (t < nb) ? g_bsum[t] : 0;
    a[t] = v;
    __syncthreads();
#pragma unroll
    for (int o = 1; o < 64; o <<= 1) {
        int u = (t >= o) ? a[t - o] : 0;
        __syncthreads();
        a[t] += u;
        __syncthreads();
    }
    if (t < nb) g_bsum[t] = a[t] - v;  // exclusive
}

// scan3: add block bases, init cursor, compute dinv (deg includes self loop)
__global__ void k_scan3() {
    int i = blockIdx.x * 1024 + threadIdx.x;
    if (i >= N_NODES) return;
    int o = g_off[i] + g_bsum[blockIdx.x];
    g_off[i] = o;
    g_cursor[i] = o;
    g_dinv[i] = rsqrtf((float)(g_degi[i] + 1));
}

__global__ void k_fill(const int* __restrict__ dst) {
    int e = blockIdx.x * blockDim.x + threadIdx.x;
    if (e >= N_EDGES) return;
    int pos = atomicAdd(&g_cursor[dst[e]], 1);
    g_eid[pos] = e;
}

// t = x @ W1 — register tiled: block 256, 64x64 tile, thread = 4 rows x 4 cols
__global__ void k_mm1(const float* __restrict__ x, const float* __restrict__ W1) {
    __shared__ float sW[64 * 64];
    __shared__ float sx[64 * 65];
    int tid = threadIdx.x;
    int row0 = blockIdx.x * 64;
    for (int i = tid; i < 4096; i += 256) sW[i] = W1[i];
    for (int i = tid; i < 4096; i += 256) {
        int r = i >> 6, k = i & 63;
        int row = row0 + r;
        sx[r * 65 + k] = (row < N_NODES) ? x[row * 64 + k] : 0.f;
    }
    __syncthreads();
    int ty = tid >> 4, tx = tid & 15;
    float4 acc0 = {0,0,0,0}, acc1 = {0,0,0,0}, acc2 = {0,0,0,0}, acc3 = {0,0,0,0};
    const float4* sW4 = (const float4*)sW;
    int rb = ty * 4;
#pragma unroll
    for (int k = 0; k < 64; k++) {
        float4 w = sW4[k * 16 + tx];
        float x0 = sx[(rb + 0) * 65 + k];
        float x1 = sx[(rb + 1) * 65 + k];
        float x2 = sx[(rb + 2) * 65 + k];
        float x3 = sx[(rb + 3) * 65 + k];
        acc0.x += x0 * w.x; acc0.y += x0 * w.y; acc0.z += x0 * w.z; acc0.w += x0 * w.w;
        acc1.x += x1 * w.x; acc1.y += x1 * w.y; acc1.z += x1 * w.z; acc1.w += x1 * w.w;
        acc2.x += x2 * w.x; acc2.y += x2 * w.y; acc2.z += x2 * w.z; acc2.w += x2 * w.w;
        acc3.x += x3 * w.x; acc3.y += x3 * w.y; acc3.z += x3 * w.z; acc3.w += x3 * w.w;
    }
    float4* t4 = (float4*)g_t;
    int row = row0 + rb;
    if (row + 0 < N_NODES) t4[(row + 0) * 16 + tx] = acc0;
    if (row + 1 < N_NODES) t4[(row + 1) * 16 + tx] = acc1;
    if (row + 2 < N_NODES) t4[(row + 2) * 16 + tx] = acc2;
    if (row + 3 < N_NODES) t4[(row + 3) * 16 + tx] = acc3;
}

// CSR gather-reduce: agg[n] = t[n]*dinv[n]^2 + sum_e t[src[e]]*dinv[src]*dinv[n]
// 16 threads per node, each owns one float4 column group. No atomics.
__global__ void k_agg(const int* __restrict__ src) {
    unsigned int gid = blockIdx.x * blockDim.x + threadIdx.x;
    unsigned int n = gid >> 4;
    int c = gid & 15;
    if (n >= N_NODES) return;
    const float4* t4 = (const float4*)g_t;
    float dn = g_dinv[n];
    float4 v = t4[n * 16 + c];
    float w2 = dn * dn;
    float4 acc = make_float4(v.x * w2, v.y * w2, v.z * w2, v.w * w2);
    int beg = g_off[n];
    int end = beg + g_degi[n];
    for (int j = beg; j < end; j++) {
        int e = g_eid[j];              // broadcast across the 16-thread group
        int s = src[e];
        float w = dn * g_dinv[s];
        float4 u = t4[s * 16 + c];
        acc.x += u.x * w; acc.y += u.y * w; acc.z += u.z * w; acc.w += u.w * w;
    }
    ((float4*)g_agg)[n * 16 + c] = acc;
}

// h = relu(agg + b1); P = [h@Wm1[0:64]+bm1 | h@Wm1[64:128]]
// register tiled: block 256, 64 rows x 128 cols, thread = 4 rows x 8 cols
__global__ void k_mm2(const float* __restrict__ Wm1, const float* __restrict__ b1,
                      const float* __restrict__ bm1) {
    __shared__ float sW[64 * 128];  // [k][0:64]=Wm1[k], [k][64:128]=Wm1[64+k]
    __shared__ float sh[64 * 65];
    int tid = threadIdx.x;
    int row0 = blockIdx.x * 64;
    for (int i = tid; i < 4096; i += 256) {
        int k = i >> 6, j = i & 63;
        sW[k * 128 + j]      = Wm1[k * 64 + j];
        sW[k * 128 + 64 + j] = Wm1[(64 + k) * 64 + j];
    }
    for (int i = tid; i < 4096; i += 256) {
        int r = i >> 6, k = i & 63;
        int row = row0 + r;
        sh[r * 65 + k] = (row < N_NODES) ? fmaxf(g_agg[row * 64 + k] + b1[k], 0.f) : 0.f;
    }
    __syncthreads();
    int ty = tid >> 4, tx = tid & 15;
    float4 a0 = {0,0,0,0}, a1 = {0,0,0,0}, a2 = {0,0,0,0}, a3 = {0,0,0,0};
    float4 b0 = {0,0,0,0}, b1v = {0,0,0,0}, b2 = {0,0,0,0}, b3 = {0,0,0,0};
    const float4* sW4 = (const float4*)sW;
    int rb = ty * 4;
#pragma unroll
    for (int k = 0; k < 64; k++) {
        float4 wa = sW4[k * 32 + tx * 2 + 0];
        float4 wb = sW4[k * 32 + tx * 2 + 1];
        float h0 = sh[(rb + 0) * 65 + k];
        float h1 = sh[(rb + 1) * 65 + k];
        float h2 = sh[(rb + 2) * 65 + k];
        float h3 = sh[(rb + 3) * 65 + k];
        a0.x += h0*wa.x; a0.y += h0*wa.y; a0.z += h0*wa.z; a0.w += h0*wa.w;
        b0.x += h0*wb.x; b0.y += h0*wb.y; b0.z += h0*wb.z; b0.w += h0*wb.w;
        a1.x += h1*wa.x; a1.y += h1*wa.y; a1.z += h1*wa.z; a1.w += h1*wa.w;
        b1v.x += h1*wb.x; b1v.y += h1*wb.y; b1v.z += h1*wb.z; b1v.w += h1*wb.w;
        a2.x += h2*wa.x; a2.y += h2*wa.y; a2.z += h2*wa.z; a2.w += h2*wa.w;
        b2.x += h2*wb.x; b2.y += h2*wb.y; b2.z += h2*wb.z; b2.w += h2*wb.w;
        a3.x += h3*wa.x; a3.y += h3*wa.y; a3.z += h3*wa.z; a3.w += h3*wa.w;
        b3.x += h3*wb.x; b3.y += h3*wb.y; b3.z += h3*wb.z; b3.w += h3*wb.w;
    }
    // fold bm1 into A half (cols < 64, i.e. tx < 8)
    if (tx < 8) {
        float4 ba = ((const float4*)bm1)[tx * 2 + 0];
        float4 bb = ((const float4*)bm1)[tx * 2 + 1];
        a0.x += ba.x; a0.y += ba.y; a0.z += ba.z; a0.w += ba.w;
        b0.x += bb.x; b0.y += bb.y; b0.z += bb.z; b0.w += bb.w;
        a1.x += ba.x; a1.y += ba.y; a1.z += ba.z; a1.w += ba.w;
        b1v.x += bb.x; b1v.y += bb.y; b1v.z += bb.z; b1v.w += bb.w;
        a2.x += ba.x; a2.y += ba.y; a2.z += ba.z; a2.w += ba.w;
        b2.x += bb.x; b2.y += bb.y; b2.z += bb.z; b2.w += bb.w;
        a3.x += ba.x; a3.y += ba.y; a3.z += ba.z; a3.w += ba.w;
        b3.x += bb.x; b3.y += bb.y; b3.z += bb.z; b3.w += bb.w;
    }
    float4* P4 = (float4*)g_P;
    int row = row0 + rb;
    if (row + 0 < N_NODES) { P4[(row+0)*32 + tx*2] = a0; P4[(row+0)*32 + tx*2+1] = b0; }
    if (row + 1 < N_NODES) { P4[(row+1)*32 + tx*2] = a1; P4[(row+1)*32 + tx*2+1] = b1v; }
    if (row + 2 < N_NODES) { P4[(row+2)*32 + tx*2] = a2; P4[(row+2)*32 + tx*2+1] = b2; }
    if (row + 3 < N_NODES) { P4[(row+3)*32 + tx*2] = a3; P4[(row+3)*32 + tx*2+1] = b3; }
}

// per-edge: hidden = relu(A[src] + B[dst] + ea@We); out = sigmoid(hidden . Wm2 + bm2)
__global__ void k_edge(const int* __restrict__ src, const int* __restrict__ dst,
                       const float* __restrict__ ea, const float* __restrict__ Wm1,
                       const float* __restrict__ Wm2, const float* __restrict__ bm2,
                       float* __restrict__ out) {
    __shared__ float4 sWe[16 * 16];  // Wm1 rows 128..143 as [k][jg]
    __shared__ float sW2[64];
    __shared__ float sb2;
    int tid = threadIdx.x;
    {
        int k = tid >> 4, jg = tid & 15;
        sWe[tid] = ((const float4*)(Wm1 + (128 + k) * 64))[jg];
    }
    if (tid < 64) sW2[tid] = Wm2[tid];
    if (tid == 0) sb2 = bm2[0];
    __syncthreads();
    unsigned int e = blockIdx.x * blockDim.x + tid;
    if (e >= N_EDGES) return;
    int s = src[e], d = dst[e];
    const float4* Ps = (const float4*)(g_P + s * 128);
    const float4* Pd = (const float4*)(g_P + d * 128 + 64);
    float eav[16];
    const float4* ea4 = (const float4*)(ea + (size_t)e * 16);
#pragma unroll
    for (int q = 0; q < 4; q++) {
        float4 v = ea4[q];
        eav[4 * q] = v.x; eav[4 * q + 1] = v.y; eav[4 * q + 2] = v.z; eav[4 * q + 3] = v.w;
    }
    float acc = 0.f;
#pragma unroll
    for (int jg = 0; jg < 16; jg++) {
        float4 a = Ps[jg];
        float4 b = Pd[jg];
        float4 v = make_float4(a.x + b.x, a.y + b.y, a.z + b.z, a.w + b.w);
#pragma unroll
        for (int k = 0; k < 16; k++) {
            float ek = eav[k];
            float4 w = sWe[k * 16 + jg];
            v.x += ek * w.x; v.y += ek * w.y; v.z += ek * w.z; v.w += ek * w.w;
        }
        v.x = fmaxf(v.x, 0.f); v.y = fmaxf(v.y, 0.f);
        v.z = fmaxf(v.z, 0.f); v.w = fmaxf(v.w, 0.f);
        acc += v.x * sW2[4 * jg] + v.y * sW2[4 * jg + 1]
             + v.z * sW2[4 * jg + 2] + v.w * sW2[4 * jg + 3];
    }
    out[e] = 1.f / (1.f + __expf(-(acc + sb2)));
}

extern "C" void kernel_launch(void* const* d_in, const int* in_sizes, int n_in,
                              void* d_out, int out_size) {
    const float* x   = (const float*)d_in[0];
    const int*   src = (const int*)d_in[1];
    const int*   dst = (const int*)d_in[2];
    const float* ea  = (const float*)d_in[3];
    const float* W1  = (const float*)d_in[4];
    const float* b1  = (const float*)d_in[5];
    const float* Wm1 = (const float*)d_in[6];
    const float* bm1 = (const float*)d_in[7];
    const float* Wm2 = (const float*)d_in[8];
    const float* bm2 = (const float*)d_in[9];
    float* out = (float*)d_out;
    (void)in_sizes; (void)n_in; (void)out_size;

    const int NB_SCAN = (N_NODES + 1023) / 1024;  // 49

    k_zero<<<(N_NODES + 255) / 256, 256>>>();
    k_count<<<(N_EDGES + 255) / 256, 256>>>(dst);
    k_mm1<<<(N_NODES + 63) / 64, 256>>>(x, W1);
    k_scan1<<<NB_SCAN, 1024>>>();
    k_scan2<<<1, 64>>>(NB_SCAN);
    k_scan3<<<NB_SCAN, 1024>>>();
    k_fill<<<(N_EDGES + 255) / 256, 256>>>(dst);
    k_agg<<<(N_NODES * 16 + 255) / 256, 256>>>(src);
    k_mm2<<<(N_NODES + 63) / 64, 256>>>(Wm1, b1, bm1);
    k_edge<<<(N_EDGES + 255) / 256, 256>>>(src, dst, ea, Wm1, Wm2, bm2, out);
}

// round 3
// speedup vs baseline: 1.1563x; 1.0207x over previous
#include <cuda_runtime.h>
#include <math.h>

#define N_NODES 50000
#define N_EDGES 800000

// Scratch (device globals — allocation-free per harness rules)
__device__ int   g_degi[N_NODES];
__device__ int   g_off[N_NODES];
__device__ int   g_cursor[N_NODES];
__device__ int   g_bsum[64];
__device__ int   g_esrc[N_EDGES];       // CSR payload: src node of each in-edge of n
__device__ float g_dinv[N_NODES];
__device__ __align__(16) float g_t[N_NODES * 64];     // t = x @ W1
__device__ __align__(16) float g_agg[N_NODES * 64];   // normalized aggregation
__device__ __align__(16) float g_P[N_NODES * 128];    // [A | B] per-node precompute

// ---- packed f32x2 helpers (sm_103a FFMA2 — ptxas never auto-fuses these) ----
typedef unsigned long long ull;
__device__ __forceinline__ ull pack2(float v) {
    ull r; asm("mov.b64 %0, {%1,%2};" : "=l"(r) : "f"(v), "f"(v)); return r;
}
__device__ __forceinline__ void unpack2(ull v, float& lo, float& hi) {
    asm("mov.b64 {%0,%1}, %2;" : "=f"(lo), "=f"(hi) : "l"(v));
}
__device__ __forceinline__ void fma2(ull& d, ull a, ull b) {
    asm("fma.rn.f32x2 %0, %1, %2, %0;" : "+l"(d) : "l"(a), "l"(b));
}
__device__ __forceinline__ ull add2(ull a, ull b) {
    ull r; asm("add.rn.f32x2 %0, %1, %2;" : "=l"(r) : "l"(a), "l"(b)); return r;
}

__global__ void k_zero() {
    int i = blockIdx.x * blockDim.x + threadIdx.x;
    if (i < N_NODES) g_degi[i] = 0;
}

__global__ void k_count(const int* __restrict__ dst) {
    int e = blockIdx.x * blockDim.x + threadIdx.x;
    if (e < N_EDGES) atomicAdd(&g_degi[dst[e]], 1);
}

// ---- exclusive prefix scan over g_degi (50000) -> g_off ----
__global__ void k_scan1() {
    int tid = threadIdx.x;
    int i = blockIdx.x * 1024 + tid;
    int v = (i < N_NODES) ? g_degi[i] : 0;
    int lane = tid & 31, wid = tid >> 5;
    int s = v;
#pragma unroll
    for (int o = 1; o < 32; o <<= 1) {
        int t = __shfl_up_sync(0xffffffffu, s, o);
        if (lane >= o) s += t;
    }
    __shared__ int ws[32];
    if (lane == 31) ws[wid] = s;
    __syncthreads();
    if (wid == 0) {
        int t = ws[lane];
        int ss = t;
#pragma unroll
        for (int o = 1; o < 32; o <<= 1) {
            int u = __shfl_up_sync(0xffffffffu, ss, o);
            if (lane >= o) ss += u;
        }
        ws[lane] = ss - t;
    }
    __syncthreads();
    int excl = ws[wid] + s - v;
    if (i < N_NODES) g_off[i] = excl;
    if (tid == 1023) g_bsum[blockIdx.x] = ws[31] + s;
}

__global__ void k_scan2(int nb) {
    __shared__ int a[64];
    int t = threadIdx.x;
    int v = (t < nb) ? g_bsum[t] : 0;
    a[t] = v;
    __syncthreads();
#pragma unroll
    for (int o = 1; o < 64; o <<= 1) {
        int u = (t >= o) ? a[t - o] : 0;
        __syncthreads();
        a[t] += u;
        __syncthreads();
    }
    if (t < nb) g_bsum[t] = a[t] - v;
}

__global__ void k_scan3() {
    int i = blockIdx.x * 1024 + threadIdx.x;
    if (i >= N_NODES) return;
    int o = g_off[i] + g_bsum[blockIdx.x];
    g_off[i] = o;
    g_cursor[i] = o;
    g_dinv[i] = rsqrtf((float)(g_degi[i] + 1));
}

// CSR fill: store src id directly (kills the eid->src dependent load in k_agg)
__global__ void k_fill(const int* __restrict__ src, const int* __restrict__ dst) {
    int e = blockIdx.x * blockDim.x + threadIdx.x;
    if (e >= N_EDGES) return;
    int pos = atomicAdd(&g_cursor[dst[e]], 1);
    g_esrc[pos] = src[e];
}

// t = x @ W1 — register tiled + FFMA2: block 256, 64x64 tile, thread = 4r x 4c
__global__ void k_mm1(const float* __restrict__ x, const float* __restrict__ W1) {
    __shared__ float sW[64 * 64];
    __shared__ float sx[64 * 65];
    int tid = threadIdx.x;
    int row0 = blockIdx.x * 64;
    for (int i = tid; i < 4096; i += 256) sW[i] = W1[i];
    for (int i = tid; i < 4096; i += 256) {
        int r = i >> 6, k = i & 63;
        int row = row0 + r;
        sx[r * 65 + k] = (row < N_NODES) ? x[row * 64 + k] : 0.f;
    }
    __syncthreads();
    int ty = tid >> 4, tx = tid & 15;
    ull c0a = 0, c0b = 0, c1a = 0, c1b = 0, c2a = 0, c2b = 0, c3a = 0, c3b = 0;
    const ulonglong2* sWu = (const ulonglong2*)sW;
    int rb = ty * 4;
#pragma unroll
    for (int k = 0; k < 64; k++) {
        ulonglong2 w = sWu[k * 16 + tx];
        ull X0 = pack2(sx[(rb + 0) * 65 + k]);
        ull X1 = pack2(sx[(rb + 1) * 65 + k]);
        ull X2 = pack2(sx[(rb + 2) * 65 + k]);
        ull X3 = pack2(sx[(rb + 3) * 65 + k]);
        fma2(c0a, X0, w.x); fma2(c0b, X0, w.y);
        fma2(c1a, X1, w.x); fma2(c1b, X1, w.y);
        fma2(c2a, X2, w.x); fma2(c2b, X2, w.y);
        fma2(c3a, X3, w.x); fma2(c3b, X3, w.y);
    }
    ulonglong2* t2 = (ulonglong2*)g_t;
    int row = row0 + rb;
    if (row + 0 < N_NODES) t2[(row + 0) * 16 + tx] = make_ulonglong2(c0a, c0b);
    if (row + 1 < N_NODES) t2[(row + 1) * 16 + tx] = make_ulonglong2(c1a, c1b);
    if (row + 2 < N_NODES) t2[(row + 2) * 16 + tx] = make_ulonglong2(c2a, c2b);
    if (row + 3 < N_NODES) t2[(row + 3) * 16 + tx] = make_ulonglong2(c3a, c3b);
}

// CSR gather-reduce, no atomics. 16 threads per node, one float4 column each.
__global__ void k_agg(const int* __restrict__ dummy) {
    unsigned int gid = blockIdx.x * blockDim.x + threadIdx.x;
    unsigned int n = gid >> 4;
    int c = gid & 15;
    if (n >= N_NODES) return;
    const float4* t4 = (const float4*)g_t;
    float dn = g_dinv[n];
    float4 v = t4[n * 16 + c];
    float w2 = dn * dn;
    float4 acc = make_float4(v.x * w2, v.y * w2, v.z * w2, v.w * w2);
    int beg = g_off[n];
    int end = beg + g_degi[n];
#pragma unroll 2
    for (int j = beg; j < end; j++) {
        int s = g_esrc[j];             // broadcast across the 16-thread group
        float w = dn * g_dinv[s];
        float4 u = t4[s * 16 + c];
        acc.x += u.x * w; acc.y += u.y * w; acc.z += u.z * w; acc.w += u.w * w;
    }
    ((float4*)g_agg)[n * 16 + c] = acc;
}

// h = relu(agg + b1); P = [h@Wm1[0:64]+bm1 | h@Wm1[64:128]]  (FFMA2 tiled)
__global__ void k_mm2(const float* __restrict__ Wm1, const float* __restrict__ b1,
                      const float* __restrict__ bm1) {
    __shared__ float sW[64 * 128];  // [k][0:64]=Wm1[k], [k][64:128]=Wm1[64+k]
    __shared__ float sh[64 * 65];
    int tid = threadIdx.x;
    int row0 = blockIdx.x * 64;
    for (int i = tid; i < 4096; i += 256) {
        int k = i >> 6, j = i & 63;
        sW[k * 128 + j]      = Wm1[k * 64 + j];
        sW[k * 128 + 64 + j] = Wm1[(64 + k) * 64 + j];
    }
    for (int i = tid; i < 4096; i += 256) {
        int r = i >> 6, k = i & 63;
        int row = row0 + r;
        sh[r * 65 + k] = (row < N_NODES) ? fmaxf(g_agg[row * 64 + k] + b1[k], 0.f) : 0.f;
    }
    __syncthreads();
    int ty = tid >> 4, tx = tid & 15;
    // per thread: 4 rows x 8 cols => 4 ULL accumulators per row (2 per float4 group)
    ull a0[4] = {0,0,0,0}, a1[4] = {0,0,0,0}, a2[4] = {0,0,0,0}, a3[4] = {0,0,0,0};
    const ulonglong2* sWu = (const ulonglong2*)sW;
    int rb = ty * 4;
#pragma unroll
    for (int k = 0; k < 64; k++) {
        ulonglong2 wa = sWu[k * 32 + tx * 2 + 0];
        ulonglong2 wb = sWu[k * 32 + tx * 2 + 1];
        ull H0 = pack2(sh[(rb + 0) * 65 + k]);
        ull H1 = pack2(sh[(rb + 1) * 65 + k]);
        ull H2 = pack2(sh[(rb + 2) * 65 + k]);
        ull H3 = pack2(sh[(rb + 3) * 65 + k]);
        fma2(a0[0], H0, wa.x); fma2(a0[1], H0, wa.y); fma2(a0[2], H0, wb.x); fma2(a0[3], H0, wb.y);
        fma2(a1[0], H1, wa.x); fma2(a1[1], H1, wa.y); fma2(a1[2], H1, wb.x); fma2(a1[3], H1, wb.y);
        fma2(a2[0], H2, wa.x); fma2(a2[1], H2, wa.y); fma2(a2[2], H2, wb.x); fma2(a2[3], H2, wb.y);
        fma2(a3[0], H3, wa.x); fma2(a3[1], H3, wa.y); fma2(a3[2], H3, wb.x); fma2(a3[3], H3, wb.y);
    }
    if (tx < 8) {  // fold bm1 into A half (added exactly once per edge)
        const ulonglong2* bmu = (const ulonglong2*)bm1;
        ulonglong2 ba = bmu[tx * 2 + 0];
        ulonglong2 bb = bmu[tx * 2 + 1];
        a0[0] = add2(a0[0], ba.x); a0[1] = add2(a0[1], ba.y); a0[2] = add2(a0[2], bb.x); a0[3] = add2(a0[3], bb.y);
        a1[0] = add2(a1[0], ba.x); a1[1] = add2(a1[1], ba.y); a1[2] = add2(a1[2], bb.x); a1[3] = add2(a1[3], bb.y);
        a2[0] = add2(a2[0], ba.x); a2[1] = add2(a2[1], ba.y); a2[2] = add2(a2[2], bb.x); a2[3] = add2(a2[3], bb.y);
        a3[0] = add2(a3[0], ba.x); a3[1] = add2(a3[1], ba.y); a3[2] = add2(a3[2], bb.x); a3[3] = add2(a3[3], bb.y);
    }
    ulonglong2* P2 = (ulonglong2*)g_P;
    int row = row0 + rb;
    if (row + 0 < N_NODES) { P2[(row+0)*32 + tx*2] = make_ulonglong2(a0[0], a0[1]); P2[(row+0)*32 + tx*2+1] = make_ulonglong2(a0[2], a0[3]); }
    if (row + 1 < N_NODES) { P2[(row+1)*32 + tx*2] = make_ulonglong2(a1[0], a1[1]); P2[(row+1)*32 + tx*2+1] = make_ulonglong2(a1[2], a1[3]); }
    if (row + 2 < N_NODES) { P2[(row+2)*32 + tx*2] = make_ulonglong2(a2[0], a2[1]); P2[(row+2)*32 + tx*2+1] = make_ulonglong2(a2[2], a2[3]); }
    if (row + 3 < N_NODES) { P2[(row+3)*32 + tx*2] = make_ulonglong2(a3[0], a3[1]); P2[(row+3)*32 + tx*2+1] = make_ulonglong2(a3[2], a3[3]); }
}

// per-edge: hidden = relu(A[src] + B[dst] + ea@We); out = sigmoid(hidden . Wm2 + bm2)
// FFMA2 version: 512 fma2 per edge instead of 1024 FFMA.
__global__ void k_edge(const int* __restrict__ src, const int* __restrict__ dst,
                       const float* __restrict__ ea, const float* __restrict__ Wm1,
                       const float* __restrict__ Wm2, const float* __restrict__ bm2,
                       float* __restrict__ out) {
    __shared__ ulonglong2 sWe[16 * 16];  // Wm1 rows 128..143, [k][jg] as packed float4
    __shared__ float sW2[64];
    __shared__ float sb2;
    int tid = threadIdx.x;
    {
        int k = tid >> 4, jg = tid & 15;
        sWe[tid] = ((const ulonglong2*)(Wm1 + (128 + k) * 64))[jg];
    }
    if (tid < 64) sW2[tid] = Wm2[tid];
    if (tid == 0) sb2 = bm2[0];
    __syncthreads();
    unsigned int e = blockIdx.x * blockDim.x + tid;
    if (e >= N_EDGES) return;
    int s = src[e], d = dst[e];
    const ulonglong2* Ps = (const ulonglong2*)(g_P + s * 128);
    const ulonglong2* Pd = (const ulonglong2*)(g_P + d * 128 + 64);
    ull ek2[16];
    {
        const float4* ea4 = (const float4*)(ea + (size_t)e * 16);
#pragma unroll
        for (int q = 0; q < 4; q++) {
            float4 v = ea4[q];
            ek2[4 * q + 0] = pack2(v.x); ek2[4 * q + 1] = pack2(v.y);
            ek2[4 * q + 2] = pack2(v.z); ek2[4 * q + 3] = pack2(v.w);
        }
    }
    float acc = 0.f;
#pragma unroll
    for (int jg = 0; jg < 16; jg++) {
        ulonglong2 a = Ps[jg];
        ulonglong2 b = Pd[jg];
        ull v0 = add2(a.x, b.x);
        ull v1 = add2(a.y, b.y);
#pragma unroll
        for (int k = 0; k < 16; k++) {
            ulonglong2 w = sWe[k * 16 + jg];
            fma2(v0, ek2[k], w.x);
            fma2(v1, ek2[k], w.y);
        }
        float f0, f1, f2, f3;
        unpack2(v0, f0, f1);
        unpack2(v1, f2, f3);
        f0 = fmaxf(f0, 0.f); f1 = fmaxf(f1, 0.f);
        f2 = fmaxf(f2, 0.f); f3 = fmaxf(f3, 0.f);
        acc += f0 * sW2[4 * jg] + f1 * sW2[4 * jg + 1]
             + f2 * sW2[4 * jg + 2] + f3 * sW2[4 * jg + 3];
    }
    out[e] = 1.f / (1.f + __expf(-(acc + sb2)));
}

extern "C" void kernel_launch(void* const* d_in, const int* in_sizes, int n_in,
                              void* d_out, int out_size) {
    const float* x   = (const float*)d_in[0];
    const int*   src = (const int*)d_in[1];
    const int*   dst = (const int*)d_in[2];
    const float* ea  = (const float*)d_in[3];
    const float* W1  = (const float*)d_in[4];
    const float* b1  = (const float*)d_in[5];
    const float* Wm1 = (const float*)d_in[6];
    const float* bm1 = (const float*)d_in[7];
    const float* Wm2 = (const float*)d_in[8];
    const float* bm2 = (const float*)d_in[9];
    float* out = (float*)d_out;
    (void)in_sizes; (void)n_in; (void)out_size;

    const int NB_SCAN = (N_NODES + 1023) / 1024;  // 49

    k_zero<<<(N_NODES + 255) / 256, 256>>>();
    k_count<<<(N_EDGES + 255) / 256, 256>>>(dst);
    k_mm1<<<(N_NODES + 63) / 64, 256>>>(x, W1);
    k_scan1<<<NB_SCAN, 1024>>>();
    k_scan2<<<1, 64>>>(NB_SCAN);
    k_scan3<<<NB_SCAN, 1024>>>();
    k_fill<<<(N_EDGES + 255) / 256, 256>>>(src, dst);
    k_agg<<<(N_NODES * 16 + 255) / 256, 256>>>(src);
    k_mm2<<<(N_NODES + 63) / 64, 256>>>(Wm1, b1, bm1);
    k_edge<<<(N_EDGES + 255) / 256, 256>>>(src, dst, ea, Wm1, Wm2, bm2, out);
}

// round 4
// speedup vs baseline: 1.3936x; 1.2052x over previous
#include <cuda_runtime.h>
#include <cuda_fp16.h>
#include <math.h>

#define N_NODES 50000
#define N_EDGES 800000

// Scratch (device globals — allocation-free per harness rules)
__device__ int   g_degi[N_NODES];
__device__ int   g_off[N_NODES];
__device__ int   g_cursor[N_NODES];
__device__ int   g_bsum[64];
__device__ int   g_esrc[N_EDGES];       // CSR payload: src node of each in-edge of n
__device__ float g_dinv[N_NODES];
__device__ __align__(16) float  g_t[N_NODES * 64];    // t = x @ W1
__device__ __align__(16) float  g_agg[N_NODES * 64];  // normalized aggregation
__device__ __align__(16) __half g_Ph[N_NODES * 128];  // [A | B] per-node precompute (fp16)

// ---- packed f32x2 helpers (sm_103a FFMA2 — ptxas never auto-fuses these) ----
typedef unsigned long long ull;
__device__ __forceinline__ ull pack2(float v) {
    ull r; asm("mov.b64 %0, {%1,%2};" : "=l"(r) : "f"(v), "f"(v)); return r;
}
__device__ __forceinline__ ull packf2(float2 f) {
    ull r; asm("mov.b64 %0, {%1,%2};" : "=l"(r) : "f"(f.x), "f"(f.y)); return r;
}
__device__ __forceinline__ void unpack2(ull v, float& lo, float& hi) {
    asm("mov.b64 {%0,%1}, %2;" : "=f"(lo), "=f"(hi) : "l"(v));
}
__device__ __forceinline__ void fma2(ull& d, ull a, ull b) {
    asm("fma.rn.f32x2 %0, %1, %2, %0;" : "+l"(d) : "l"(a), "l"(b));
}
__device__ __forceinline__ ull add2(ull a, ull b) {
    ull r; asm("add.rn.f32x2 %0, %1, %2;" : "=l"(r) : "l"(a), "l"(b)); return r;
}
// half2 bits -> packed f32x2
__device__ __forceinline__ ull h2tof2(unsigned int h) {
    __half2 hv = *reinterpret_cast<__half2*>(&h);
    float2 f = __half22float2(hv);
    return packf2(f);
}

__global__ void k_zero() {
    int i = blockIdx.x * blockDim.x + threadIdx.x;
    if (i < N_NODES) g_degi[i] = 0;
}

__global__ void k_count(const int* __restrict__ dst) {
    int e = blockIdx.x * blockDim.x + threadIdx.x;
    if (e < N_EDGES) atomicAdd(&g_degi[dst[e]], 1);
}

// ---- exclusive prefix scan over g_degi (50000) -> g_off ----
__global__ void k_scan1() {
    int tid = threadIdx.x;
    int i = blockIdx.x * 1024 + tid;
    int v = (i < N_NODES) ? g_degi[i] : 0;
    int lane = tid & 31, wid = tid >> 5;
    int s = v;
#pragma unroll
    for (int o = 1; o < 32; o <<= 1) {
        int t = __shfl_up_sync(0xffffffffu, s, o);
        if (lane >= o) s += t;
    }
    __shared__ int ws[32];
    if (lane == 31) ws[wid] = s;
    __syncthreads();
    if (wid == 0) {
        int t = ws[lane];
        int ss = t;
#pragma unroll
        for (int o = 1; o < 32; o <<= 1) {
            int u = __shfl_up_sync(0xffffffffu, ss, o);
            if (lane >= o) ss += u;
        }
        ws[lane] = ss - t;
    }
    __syncthreads();
    int excl = ws[wid] + s - v;
    if (i < N_NODES) g_off[i] = excl;
    if (tid == 1023) g_bsum[blockIdx.x] = ws[31] + s;
}

// scan3: per-block base via redundant smem sum of block totals (scan2 folded in),
// add base, init cursor, compute dinv (deg includes self loop)
__global__ void k_scan3(int nb) {
    __shared__ int sb[64];
    __shared__ int base_s;
    int tid = threadIdx.x;
    if (tid < 64) sb[tid] = (tid < nb) ? g_bsum[tid] : 0;
    __syncthreads();
    if (tid == 0) {
        int b = 0;
        for (int j = 0; j < (int)blockIdx.x; j++) b += sb[j];
        base_s = b;
    }
    __syncthreads();
    int i = blockIdx.x * 1024 + tid;
    if (i >= N_NODES) return;
    int o = g_off[i] + base_s;
    g_off[i] = o;
    g_cursor[i] = o;
    g_dinv[i] = rsqrtf((float)(g_degi[i] + 1));
}

// CSR fill: store src id directly
__global__ void k_fill(const int* __restrict__ src, const int* __restrict__ dst) {
    int e = blockIdx.x * blockDim.x + threadIdx.x;
    if (e >= N_EDGES) return;
    int pos = atomicAdd(&g_cursor[dst[e]], 1);
    g_esrc[pos] = src[e];
}

// t = x @ W1 — register tiled + FFMA2: block 256, 64x64 tile, thread = 4r x 4c
__global__ void k_mm1(const float* __restrict__ x, const float* __restrict__ W1) {
    __shared__ float sW[64 * 64];
    __shared__ float sx[64 * 65];
    int tid = threadIdx.x;
    int row0 = blockIdx.x * 64;
    for (int i = tid; i < 4096; i += 256) sW[i] = W1[i];
    for (int i = tid; i < 4096; i += 256) {
        int r = i >> 6, k = i & 63;
        int row = row0 + r;
        sx[r * 65 + k] = (row < N_NODES) ? x[row * 64 + k] : 0.f;
    }
    __syncthreads();
    int ty = tid >> 4, tx = tid & 15;
    ull c0a = 0, c0b = 0, c1a = 0, c1b = 0, c2a = 0, c2b = 0, c3a = 0, c3b = 0;
    const ulonglong2* sWu = (const ulonglong2*)sW;
    int rb = ty * 4;
#pragma unroll
    for (int k = 0; k < 64; k++) {
        ulonglong2 w = sWu[k * 16 + tx];
        ull X0 = pack2(sx[(rb + 0) * 65 + k]);
        ull X1 = pack2(sx[(rb + 1) * 65 + k]);
        ull X2 = pack2(sx[(rb + 2) * 65 + k]);
        ull X3 = pack2(sx[(rb + 3) * 65 + k]);
        fma2(c0a, X0, w.x); fma2(c0b, X0, w.y);
        fma2(c1a, X1, w.x); fma2(c1b, X1, w.y);
        fma2(c2a, X2, w.x); fma2(c2b, X2, w.y);
        fma2(c3a, X3, w.x); fma2(c3b, X3, w.y);
    }
    ulonglong2* t2 = (ulonglong2*)g_t;
    int row = row0 + rb;
    if (row + 0 < N_NODES) t2[(row + 0) * 16 + tx] = make_ulonglong2(c0a, c0b);
    if (row + 1 < N_NODES) t2[(row + 1) * 16 + tx] = make_ulonglong2(c1a, c1b);
    if (row + 2 < N_NODES) t2[(row + 2) * 16 + tx] = make_ulonglong2(c2a, c2b);
    if (row + 3 < N_NODES) t2[(row + 3) * 16 + tx] = make_ulonglong2(c3a, c3b);
}

// CSR gather-reduce, no atomics. 16 threads per node, one float4 column each.
__global__ void k_agg(const int* __restrict__ dummy) {
    unsigned int gid = blockIdx.x * blockDim.x + threadIdx.x;
    unsigned int n = gid >> 4;
    int c = gid & 15;
    if (n >= N_NODES) return;
    const float4* t4 = (const float4*)g_t;
    float dn = g_dinv[n];
    float4 v = t4[n * 16 + c];
    float w2 = dn * dn;
    float4 acc = make_float4(v.x * w2, v.y * w2, v.z * w2, v.w * w2);
    int beg = g_off[n];
    int end = beg + g_degi[n];
#pragma unroll 4
    for (int j = beg; j < end; j++) {
        int s = g_esrc[j];             // broadcast across the 16-thread group
        float w = dn * g_dinv[s];
        float4 u = t4[s * 16 + c];
        acc.x += u.x * w; acc.y += u.y * w; acc.z += u.z * w; acc.w += u.w * w;
    }
    ((float4*)g_agg)[n * 16 + c] = acc;
}

// h = relu(agg + b1); P = [h@Wm1[0:64]+bm1 | h@Wm1[64:128]] stored fp16
__global__ void k_mm2(const float* __restrict__ Wm1, const float* __restrict__ b1,
                      const float* __restrict__ bm1) {
    __shared__ float sW[64 * 128];  // [k][0:64]=Wm1[k], [k][64:128]=Wm1[64+k]
    __shared__ float sh[64 * 65];
    int tid = threadIdx.x;
    int row0 = blockIdx.x * 64;
    for (int i = tid; i < 4096; i += 256) {
        int k = i >> 6, j = i & 63;
        sW[k * 128 + j]      = Wm1[k * 64 + j];
        sW[k * 128 + 64 + j] = Wm1[(64 + k) * 64 + j];
    }
    for (int i = tid; i < 4096; i += 256) {
        int r = i >> 6, k = i & 63;
        int row = row0 + r;
        sh[r * 65 + k] = (row < N_NODES) ? fmaxf(g_agg[row * 64 + k] + b1[k], 0.f) : 0.f;
    }
    __syncthreads();
    int ty = tid >> 4, tx = tid & 15;
    ull a0[4] = {0,0,0,0}, a1[4] = {0,0,0,0}, a2[4] = {0,0,0,0}, a3[4] = {0,0,0,0};
    const ulonglong2* sWu = (const ulonglong2*)sW;
    int rb = ty * 4;
#pragma unroll
    for (int k = 0; k < 64; k++) {
        ulonglong2 wa = sWu[k * 32 + tx * 2 + 0];
        ulonglong2 wb = sWu[k * 32 + tx * 2 + 1];
        ull H0 = pack2(sh[(rb + 0) * 65 + k]);
        ull H1 = pack2(sh[(rb + 1) * 65 + k]);
        ull H2 = pack2(sh[(rb + 2) * 65 + k]);
        ull H3 = pack2(sh[(rb + 3) * 65 + k]);
        fma2(a0[0], H0, wa.x); fma2(a0[1], H0, wa.y); fma2(a0[2], H0, wb.x); fma2(a0[3], H0, wb.y);
        fma2(a1[0], H1, wa.x); fma2(a1[1], H1, wa.y); fma2(a1[2], H1, wb.x); fma2(a1[3], H1, wb.y);
        fma2(a2[0], H2, wa.x); fma2(a2[1], H2, wa.y); fma2(a2[2], H2, wb.x); fma2(a2[3], H2, wb.y);
        fma2(a3[0], H3, wa.x); fma2(a3[1], H3, wa.y); fma2(a3[2], H3, wb.x); fma2(a3[3], H3, wb.y);
    }
    if (tx < 8) {  // fold bm1 into A half (added exactly once per edge)
        const ulonglong2* bmu = (const ulonglong2*)bm1;
        ulonglong2 ba = bmu[tx * 2 + 0];
        ulonglong2 bb = bmu[tx * 2 + 1];
        a0[0] = add2(a0[0], ba.x); a0[1] = add2(a0[1], ba.y); a0[2] = add2(a0[2], bb.x); a0[3] = add2(a0[3], bb.y);
        a1[0] = add2(a1[0], ba.x); a1[1] = add2(a1[1], ba.y); a1[2] = add2(a1[2], bb.x); a1[3] = add2(a1[3], bb.y);
        a2[0] = add2(a2[0], ba.x); a2[1] = add2(a2[1], ba.y); a2[2] = add2(a2[2], bb.x); a2[3] = add2(a2[3], bb.y);
        a3[0] = add2(a3[0], ba.x); a3[1] = add2(a3[1], ba.y); a3[2] = add2(a3[2], bb.x); a3[3] = add2(a3[3], bb.y);
    }
    // convert 8 floats per row to 8 halves (16B) and store
    uint4* P4 = (uint4*)g_Ph;   // 8 halves per uint4; 16 uint4 per node row of 128 halves
    int row = row0 + rb;
    ull* rows[4] = {a0, a1, a2, a3};
#pragma unroll
    for (int rr = 0; rr < 4; rr++) {
        if (row + rr >= N_NODES) break;
        float lo, hi;
        uint4 u;
        unpack2(rows[rr][0], lo, hi); __half2 p0 = __floats2half2_rn(lo, hi);
        unpack2(rows[rr][1], lo, hi); __half2 p1 = __floats2half2_rn(lo, hi);
        unpack2(rows[rr][2], lo, hi); __half2 p2 = __floats2half2_rn(lo, hi);
        unpack2(rows[rr][3], lo, hi); __half2 p3 = __floats2half2_rn(lo, hi);
        u.x = *(unsigned int*)&p0; u.y = *(unsigned int*)&p1;
        u.z = *(unsigned int*)&p2; u.w = *(unsigned int*)&p3;
        P4[(row + rr) * 16 + tx] = u;   // 8 cols starting at 8*tx
    }
}

// per-edge: hidden = relu(A[src] + B[dst] + ea@We); out = sigmoid(hidden . Wm2 + bm2)
// P rows loaded as fp16 (128B per edge endpoint half), math in packed f32x2.
__global__ void k_edge(const int* __restrict__ src, const int* __restrict__ dst,
                       const float* __restrict__ ea, const float* __restrict__ Wm1,
                       const float* __restrict__ Wm2, const float* __restrict__ bm2,
                       float* __restrict__ out) {
    __shared__ ull sWe[16 * 32];  // Wm1 rows 128..143: [k][col-pair j2]
    __shared__ float sW2[64];
    __shared__ float sb2;
    int tid = threadIdx.x;
    for (int i = tid; i < 512; i += 256) {
        int k = i >> 5, j2 = i & 31;
        const float2* wrow = (const float2*)(Wm1 + (128 + k) * 64);
        sWe[i] = packf2(wrow[j2]);
    }
    if (tid < 64) sW2[tid] = Wm2[tid];
    if (tid == 0) sb2 = bm2[0];
    __syncthreads();
    unsigned int e = blockIdx.x * blockDim.x + tid;
    if (e >= N_EDGES) return;
    int s = src[e], d = dst[e];
    const uint4* PsA = (const uint4*)(g_Ph + s * 128);        // A half: 8 uint4
    const uint4* PdB = (const uint4*)(g_Ph + d * 128 + 64);   // B half: 8 uint4
    ull ek2[16];
    {
        const float4* ea4 = (const float4*)(ea + (size_t)e * 16);
#pragma unroll
        for (int q = 0; q < 4; q++) {
            float4 v = ea4[q];
            ek2[4 * q + 0] = pack2(v.x); ek2[4 * q + 1] = pack2(v.y);
            ek2[4 * q + 2] = pack2(v.z); ek2[4 * q + 3] = pack2(v.w);
        }
    }
    float acc = 0.f;
#pragma unroll
    for (int jg8 = 0; jg8 < 8; jg8++) {   // 8 cols per iteration
        uint4 au = PsA[jg8];
        uint4 bu = PdB[jg8];
        ull v0 = add2(h2tof2(au.x), h2tof2(bu.x));
        ull v1 = add2(h2tof2(au.y), h2tof2(bu.y));
        ull v2 = add2(h2tof2(au.z), h2tof2(bu.z));
        ull v3 = add2(h2tof2(au.w), h2tof2(bu.w));
#pragma unroll
        for (int k = 0; k < 16; k++) {
            const ull* w = &sWe[k * 32 + jg8 * 4];
            fma2(v0, ek2[k], w[0]);
            fma2(v1, ek2[k], w[1]);
            fma2(v2, ek2[k], w[2]);
            fma2(v3, ek2[k], w[3]);
        }
        float f0, f1, f2, f3, f4, f5, f6, f7;
        unpack2(v0, f0, f1); unpack2(v1, f2, f3);
        unpack2(v2, f4, f5); unpack2(v3, f6, f7);
        f0 = fmaxf(f0, 0.f); f1 = fmaxf(f1, 0.f); f2 = fmaxf(f2, 0.f); f3 = fmaxf(f3, 0.f);
        f4 = fmaxf(f4, 0.f); f5 = fmaxf(f5, 0.f); f6 = fmaxf(f6, 0.f); f7 = fmaxf(f7, 0.f);
        const float* w2 = &sW2[jg8 * 8];
        acc += f0 * w2[0] + f1 * w2[1] + f2 * w2[2] + f3 * w2[3]
             + f4 * w2[4] + f5 * w2[5] + f6 * w2[6] + f7 * w2[7];
    }
    out[e] = 1.f / (1.f + __expf(-(acc + sb2)));
}

extern "C" void kernel_launch(void* const* d_in, const int* in_sizes, int n_in,
                              void* d_out, int out_size) {
    const float* x   = (const float*)d_in[0];
    const int*   src = (const int*)d_in[1];
    const int*   dst = (const int*)d_in[2];
    const float* ea  = (const float*)d_in[3];
    const float* W1  = (const float*)d_in[4];
    const float* b1  = (const float*)d_in[5];
    const float* Wm1 = (const float*)d_in[6];
    const float* bm1 = (const float*)d_in[7];
    const float* Wm2 = (const float*)d_in[8];
    const float* bm2 = (const float*)d_in[9];
    float* out = (float*)d_out;
    (void)in_sizes; (void)n_in; (void)out_size;

    const int NB_SCAN = (N_NODES + 1023) / 1024;  // 49

    k_zero<<<(N_NODES + 255) / 256, 256>>>();
    k_count<<<(N_EDGES + 255) / 256, 256>>>(dst);
    k_scan1<<<NB_SCAN, 1024>>>();
    k_mm1<<<(N_NODES + 63) / 64, 256>>>(x, W1);   // launch #4 → ncu capture slot
    k_scan3<<<NB_SCAN, 1024>>>(NB_SCAN);
    k_fill<<<(N_EDGES + 255) / 256, 256>>>(src, dst);
    k_agg<<<(N_NODES * 16 + 255) / 256, 256>>>(src);
    k_mm2<<<(N_NODES + 63) / 64, 256>>>(Wm1, b1, bm1);
    k_edge<<<(N_EDGES + 255) / 256, 256>>>(src, dst, ea, Wm1, Wm2, bm2, out);
}

// round 5
// speedup vs baseline: 1.4495x; 1.0401x over previous
#include <cuda_runtime.h>
#include <cuda_fp16.h>
#include <math.h>

#define N_NODES 50000
#define N_EDGES 800000

// Scratch (device globals — allocation-free per harness rules)
__device__ int   g_degi[N_NODES];
__device__ int   g_off[N_NODES];
__device__ int   g_cursor[N_NODES];
__device__ int   g_bsum[64];
__device__ int   g_esrc[N_EDGES];       // CSR payload: src node of each in-edge of n
__device__ float g_dinv[N_NODES];
__device__ __align__(16) float  g_t[N_NODES * 64];    // t = x @ W1
__device__ __align__(16) float  g_agg[N_NODES * 64];  // normalized aggregation
__device__ __align__(16) __half g_Ph[N_NODES * 128];  // [A | B] per-node precompute (fp16)

// ---- packed f32x2 helpers (sm_103a FFMA2 — ptxas never auto-fuses these) ----
typedef unsigned long long ull;
__device__ __forceinline__ ull pack2(float v) {
    ull r; asm("mov.b64 %0, {%1,%2};" : "=l"(r) : "f"(v), "f"(v)); return r;
}
__device__ __forceinline__ ull packf2(float2 f) {
    ull r; asm("mov.b64 %0, {%1,%2};" : "=l"(r) : "f"(f.x), "f"(f.y)); return r;
}
__device__ __forceinline__ void unpack2(ull v, float& lo, float& hi) {
    asm("mov.b64 {%0,%1}, %2;" : "=f"(lo), "=f"(hi) : "l"(v));
}
__device__ __forceinline__ void fma2(ull& d, ull a, ull b) {
    asm("fma.rn.f32x2 %0, %1, %2, %0;" : "+l"(d) : "l"(a), "l"(b));
}
__device__ __forceinline__ ull add2(ull a, ull b) {
    ull r; asm("add.rn.f32x2 %0, %1, %2;" : "=l"(r) : "l"(a), "l"(b)); return r;
}
// half2 bits -> packed f32x2
__device__ __forceinline__ ull h2tof2(unsigned int h) {
    __half2 hv = *reinterpret_cast<__half2*>(&h);
    float2 f = __half22float2(hv);
    return packf2(f);
}

__global__ void k_zero() {
    int i = blockIdx.x * blockDim.x + threadIdx.x;
    if (i < N_NODES) g_degi[i] = 0;
}

__global__ void k_count(const int* __restrict__ dst) {
    int e = blockIdx.x * blockDim.x + threadIdx.x;
    if (e < N_EDGES) atomicAdd(&g_degi[dst[e]], 1);
}

// ---- exclusive prefix scan over g_degi (50000) -> g_off ----
__global__ void k_scan1() {
    int tid = threadIdx.x;
    int i = blockIdx.x * 1024 + tid;
    int v = (i < N_NODES) ? g_degi[i] : 0;
    int lane = tid & 31, wid = tid >> 5;
    int s = v;
#pragma unroll
    for (int o = 1; o < 32; o <<= 1) {
        int t = __shfl_up_sync(0xffffffffu, s, o);
        if (lane >= o) s += t;
    }
    __shared__ int ws[32];
    if (lane == 31) ws[wid] = s;
    __syncthreads();
    if (wid == 0) {
        int t = ws[lane];
        int ss = t;
#pragma unroll
        for (int o = 1; o < 32; o <<= 1) {
            int u = __shfl_up_sync(0xffffffffu, ss, o);
            if (lane >= o) ss += u;
        }
        ws[lane] = ss - t;
    }
    __syncthreads();
    int excl = ws[wid] + s - v;
    if (i < N_NODES) g_off[i] = excl;
    if (tid == 1023) g_bsum[blockIdx.x] = ws[31] + s;
}

// scan3: per-block base via redundant smem sum of block totals,
// add base, init cursor, compute dinv (deg includes self loop)
__global__ void k_scan3(int nb) {
    __shared__ int sb[64];
    __shared__ int base_s;
    int tid = threadIdx.x;
    if (tid < 64) sb[tid] = (tid < nb) ? g_bsum[tid] : 0;
    __syncthreads();
    if (tid == 0) {
        int b = 0;
        for (int j = 0; j < (int)blockIdx.x; j++) b += sb[j];
        base_s = b;
    }
    __syncthreads();
    int i = blockIdx.x * 1024 + tid;
    if (i >= N_NODES) return;
    int o = g_off[i] + base_s;
    g_off[i] = o;
    g_cursor[i] = o;
    g_dinv[i] = rsqrtf((float)(g_degi[i] + 1));
}

// CSR fill: store src id directly
__global__ void k_fill(const int* __restrict__ src, const int* __restrict__ dst) {
    int e = blockIdx.x * blockDim.x + threadIdx.x;
    if (e >= N_EDGES) return;
    int pos = atomicAdd(&g_cursor[dst[e]], 1);
    g_esrc[pos] = src[e];
}

// t = x @ W1 — k-major activation tile: per k-step 2 LDS.128 feed 8 FFMA2.
// block 256, 64x64 tile, thread = 4 rows x 4 cols
__global__ void k_mm1(const float* __restrict__ x, const float* __restrict__ W1) {
    __shared__ float sW[64 * 64];       // [k][j]
    __shared__ float sx[64 * 68];       // k-major: sx[k*68 + r]
    int tid = threadIdx.x;
    int row0 = blockIdx.x * 64;
    for (int i = tid; i < 4096; i += 256) sW[i] = W1[i];
    for (int i = tid; i < 4096; i += 256) {
        int r = i >> 6, k = i & 63;
        int row = row0 + r;
        sx[k * 68 + r] = (row < N_NODES) ? x[row * 64 + k] : 0.f;
    }
    __syncthreads();
    int ty = tid >> 4, tx = tid & 15;
    ull c0a = 0, c0b = 0, c1a = 0, c1b = 0, c2a = 0, c2b = 0, c3a = 0, c3b = 0;
    const ulonglong2* sWu = (const ulonglong2*)sW;
    int rb = ty * 4;
#pragma unroll
    for (int k = 0; k < 64; k++) {
        ulonglong2 w = sWu[k * 16 + tx];
        float4 xv = *(const float4*)&sx[k * 68 + rb];   // 4 rows at this k
        ull X0 = pack2(xv.x), X1 = pack2(xv.y), X2 = pack2(xv.z), X3 = pack2(xv.w);
        fma2(c0a, X0, w.x); fma2(c0b, X0, w.y);
        fma2(c1a, X1, w.x); fma2(c1b, X1, w.y);
        fma2(c2a, X2, w.x); fma2(c2b, X2, w.y);
        fma2(c3a, X3, w.x); fma2(c3b, X3, w.y);
    }
    ulonglong2* t2 = (ulonglong2*)g_t;
    int row = row0 + rb;
    if (row + 0 < N_NODES) t2[(row + 0) * 16 + tx] = make_ulonglong2(c0a, c0b);
    if (row + 1 < N_NODES) t2[(row + 1) * 16 + tx] = make_ulonglong2(c1a, c1b);
    if (row + 2 < N_NODES) t2[(row + 2) * 16 + tx] = make_ulonglong2(c2a, c2b);
    if (row + 3 < N_NODES) t2[(row + 3) * 16 + tx] = make_ulonglong2(c3a, c3b);
}

// CSR gather-reduce, no atomics. 16 threads per node, one float4 column each.
__global__ void k_agg(const int* __restrict__ dummy) {
    unsigned int gid = blockIdx.x * blockDim.x + threadIdx.x;
    unsigned int n = gid >> 4;
    int c = gid & 15;
    if (n >= N_NODES) return;
    const float4* t4 = (const float4*)g_t;
    float dn = g_dinv[n];
    float4 v = t4[n * 16 + c];
    float w2 = dn * dn;
    float4 acc = make_float4(v.x * w2, v.y * w2, v.z * w2, v.w * w2);
    int beg = g_off[n];
    int end = beg + g_degi[n];
#pragma unroll 4
    for (int j = beg; j < end; j++) {
        int s = g_esrc[j];             // broadcast across the 16-thread group
        float w = dn * g_dinv[s];
        float4 u = t4[s * 16 + c];
        acc.x += u.x * w; acc.y += u.y * w; acc.z += u.z * w; acc.w += u.w * w;
    }
    ((float4*)g_agg)[n * 16 + c] = acc;
}

// h = relu(agg + b1); P = [h@Wm1[0:64]+bm1 | h@Wm1[64:128]] stored fp16
// k-major h tile: per k-step 3 LDS.128 feed 16 FFMA2.
__global__ void k_mm2(const float* __restrict__ Wm1, const float* __restrict__ b1,
                      const float* __restrict__ bm1) {
    __shared__ float sW[64 * 128];  // [k][0:64]=Wm1[k], [k][64:128]=Wm1[64+k]
    __shared__ float sh[64 * 68];   // k-major: sh[k*68 + r]
    int tid = threadIdx.x;
    int row0 = blockIdx.x * 64;
    for (int i = tid; i < 4096; i += 256) {
        int k = i >> 6, j = i & 63;
        sW[k * 128 + j]      = Wm1[k * 64 + j];
        sW[k * 128 + 64 + j] = Wm1[(64 + k) * 64 + j];
    }
    for (int i = tid; i < 4096; i += 256) {
        int r = i >> 6, k = i & 63;
        int row = row0 + r;
        sh[k * 68 + r] = (row < N_NODES) ? fmaxf(g_agg[row * 64 + k] + b1[k], 0.f) : 0.f;
    }
    __syncthreads();
    int ty = tid >> 4, tx = tid & 15;
    ull a0[4] = {0,0,0,0}, a1[4] = {0,0,0,0}, a2[4] = {0,0,0,0}, a3[4] = {0,0,0,0};
    const ulonglong2* sWu = (const ulonglong2*)sW;
    int rb = ty * 4;
#pragma unroll
    for (int k = 0; k < 64; k++) {
        ulonglong2 wa = sWu[k * 32 + tx * 2 + 0];
        ulonglong2 wb = sWu[k * 32 + tx * 2 + 1];
        float4 hv = *(const float4*)&sh[k * 68 + rb];
        ull H0 = pack2(hv.x), H1 = pack2(hv.y), H2 = pack2(hv.z), H3 = pack2(hv.w);
        fma2(a0[0], H0, wa.x); fma2(a0[1], H0, wa.y); fma2(a0[2], H0, wb.x); fma2(a0[3], H0, wb.y);
        fma2(a1[0], H1, wa.x); fma2(a1[1], H1, wa.y); fma2(a1[2], H1, wb.x); fma2(a1[3], H1, wb.y);
        fma2(a2[0], H2, wa.x); fma2(a2[1], H2, wa.y); fma2(a2[2], H2, wb.x); fma2(a2[3], H2, wb.y);
        fma2(a3[0], H3, wa.x); fma2(a3[1], H3, wa.y); fma2(a3[2], H3, wb.x); fma2(a3[3], H3, wb.y);
    }
    if (tx < 8) {  // fold bm1 into A half (added exactly once per edge)
        const ulonglong2* bmu = (const ulonglong2*)bm1;
        ulonglong2 ba = bmu[tx * 2 + 0];
        ulonglong2 bb = bmu[tx * 2 + 1];
        a0[0] = add2(a0[0], ba.x); a0[1] = add2(a0[1], ba.y); a0[2] = add2(a0[2], bb.x); a0[3] = add2(a0[3], bb.y);
        a1[0] = add2(a1[0], ba.x); a1[1] = add2(a1[1], ba.y); a1[2] = add2(a1[2], bb.x); a1[3] = add2(a1[3], bb.y);
        a2[0] = add2(a2[0], ba.x); a2[1] = add2(a2[1], ba.y); a2[2] = add2(a2[2], bb.x); a2[3] = add2(a2[3], bb.y);
        a3[0] = add2(a3[0], ba.x); a3[1] = add2(a3[1], ba.y); a3[2] = add2(a3[2], bb.x); a3[3] = add2(a3[3], bb.y);
    }
    uint4* P4 = (uint4*)g_Ph;
    int row = row0 + rb;
    ull* rows[4] = {a0, a1, a2, a3};
#pragma unroll
    for (int rr = 0; rr < 4; rr++) {
        if (row + rr >= N_NODES) break;
        float lo, hi;
        uint4 u;
        unpack2(rows[rr][0], lo, hi); __half2 p0 = __floats2half2_rn(lo, hi);
        unpack2(rows[rr][1], lo, hi); __half2 p1 = __floats2half2_rn(lo, hi);
        unpack2(rows[rr][2], lo, hi); __half2 p2 = __floats2half2_rn(lo, hi);
        unpack2(rows[rr][3], lo, hi); __half2 p3 = __floats2half2_rn(lo, hi);
        u.x = *(unsigned int*)&p0; u.y = *(unsigned int*)&p1;
        u.z = *(unsigned int*)&p2; u.w = *(unsigned int*)&p3;
        P4[(row + rr) * 16 + tx] = u;   // 8 cols starting at 8*tx
    }
}

// per-edge: hidden = relu(A[src] + B[dst] + ea@We); out = sigmoid(hidden . Wm2 + bm2)
__global__ void k_edge(const int* __restrict__ src, const int* __restrict__ dst,
                       const float* __restrict__ ea, const float* __restrict__ Wm1,
                       const float* __restrict__ Wm2, const float* __restrict__ bm2,
                       float* __restrict__ out) {
    __shared__ ull sWe[16 * 32];  // Wm1 rows 128..143: [k][col-pair j2]
    __shared__ float sW2[64];
    __shared__ float sb2;
    int tid = threadIdx.x;
    for (int i = tid; i < 512; i += 256) {
        int k = i >> 5, j2 = i & 31;
        const float2* wrow = (const float2*)(Wm1 + (128 + k) * 64);
        sWe[i] = packf2(wrow[j2]);
    }
    if (tid < 64) sW2[tid] = Wm2[tid];
    if (tid == 0) sb2 = bm2[0];
    __syncthreads();
    unsigned int e = blockIdx.x * blockDim.x + tid;
    if (e >= N_EDGES) return;
    int s = src[e], d = dst[e];
    const uint4* PsA = (const uint4*)(g_Ph + s * 128);        // A half: 8 uint4
    const uint4* PdB = (const uint4*)(g_Ph + d * 128 + 64);   // B half: 8 uint4
    ull ek2[16];
    {
        const float4* ea4 = (const float4*)(ea + (size_t)e * 16);
#pragma unroll
        for (int q = 0; q < 4; q++) {
            float4 v = ea4[q];
            ek2[4 * q + 0] = pack2(v.x); ek2[4 * q + 1] = pack2(v.y);
            ek2[4 * q + 2] = pack2(v.z); ek2[4 * q + 3] = pack2(v.w);
        }
    }
    float acc = 0.f;
#pragma unroll
    for (int jg8 = 0; jg8 < 8; jg8++) {   // 8 cols per iteration
        uint4 au = PsA[jg8];
        uint4 bu = PdB[jg8];
        ull v0 = add2(h2tof2(au.x), h2tof2(bu.x));
        ull v1 = add2(h2tof2(au.y), h2tof2(bu.y));
        ull v2 = add2(h2tof2(au.z), h2tof2(bu.z));
        ull v3 = add2(h2tof2(au.w), h2tof2(bu.w));
#pragma unroll
        for (int k = 0; k < 16; k++) {
            const ull* w = &sWe[k * 32 + jg8 * 4];
            fma2(v0, ek2[k], w[0]);
            fma2(v1, ek2[k], w[1]);
            fma2(v2, ek2[k], w[2]);
            fma2(v3, ek2[k], w[3]);
        }
        float f0, f1, f2, f3, f4, f5, f6, f7;
        unpack2(v0, f0, f1); unpack2(v1, f2, f3);
        unpack2(v2, f4, f5); unpack2(v3, f6, f7);
        f0 = fmaxf(f0, 0.f); f1 = fmaxf(f1, 0.f); f2 = fmaxf(f2, 0.f); f3 = fmaxf(f3, 0.f);
        f4 = fmaxf(f4, 0.f); f5 = fmaxf(f5, 0.f); f6 = fmaxf(f6, 0.f); f7 = fmaxf(f7, 0.f);
        const float* w2 = &sW2[jg8 * 8];
        acc += f0 * w2[0] + f1 * w2[1] + f2 * w2[2] + f3 * w2[3]
             + f4 * w2[4] + f5 * w2[5] + f6 * w2[6] + f7 * w2[7];
    }
    out[e] = 1.f / (1.f + __expf(-(acc + sb2)));
}

extern "C" void kernel_launch(void* const* d_in, const int* in_sizes, int n_in,
                              void* d_out, int out_size) {
    const float* x   = (const float*)d_in[0];
    const int*   src = (const int*)d_in[1];
    const int*   dst = (const int*)d_in[2];
    const float* ea  = (const float*)d_in[3];
    const float* W1  = (const float*)d_in[4];
    const float* b1  = (const float*)d_in[5];
    const float* Wm1 = (const float*)d_in[6];
    const float* bm1 = (const float*)d_in[7];
    const float* Wm2 = (const float*)d_in[8];
    const float* bm2 = (const float*)d_in[9];
    float* out = (float*)d_out;
    (void)in_sizes; (void)n_in; (void)out_size;

    const int NB_SCAN = (N_NODES + 1023) / 1024;  // 49

    k_zero<<<(N_NODES + 255) / 256, 256>>>();
    k_count<<<(N_EDGES + 255) / 256, 256>>>(dst);
    k_scan1<<<NB_SCAN, 1024>>>();
    k_mm1<<<(N_NODES + 63) / 64, 256>>>(x, W1);   // launch #4 → ncu capture slot
    k_scan3<<<NB_SCAN, 1024>>>(NB_SCAN);
    k_fill<<<(N_EDGES + 255) / 256, 256>>>(src, dst);
    k_agg<<<(N_NODES * 16 + 255) / 256, 256>>>(src);
    k_mm2<<<(N_NODES + 63) / 64, 256>>>(Wm1, b1, bm1);
    k_edge<<<(N_EDGES + 255) / 256, 256>>>(src, dst, ea, Wm1, Wm2, bm2, out);
}

// round 6
// speedup vs baseline: 1.5916x; 1.0980x over previous
#include <cuda_runtime.h>
#include <cuda_fp16.h>
#include <math.h>

#define N_NODES 50000
#define N_EDGES 800000

// Scratch (device globals — allocation-free per harness rules)
__device__ int   g_degi[N_NODES];
__device__ int   g_off[N_NODES];
__device__ int   g_cursor[N_NODES];
__device__ int   g_bsum[64];
__device__ int   g_esrc[N_EDGES];       // CSR payload: src node of each in-edge of n
__device__ float g_dinv[N_NODES];
__device__ __align__(16) __half g_th[N_NODES * 64];   // t = x @ W1 (fp16)
__device__ __align__(16) float  g_agg[N_NODES * 64];  // normalized aggregation
__device__ __align__(16) __half g_Ph[N_NODES * 128];  // [A | B] per-node precompute (fp16)

// ---- packed f32x2 helpers (sm_103a FFMA2 — ptxas never auto-fuses these) ----
typedef unsigned long long ull;
__device__ __forceinline__ ull pack2(float v) {
    ull r; asm("mov.b64 %0, {%1,%2};" : "=l"(r) : "f"(v), "f"(v)); return r;
}
__device__ __forceinline__ ull packf2(float2 f) {
    ull r; asm("mov.b64 %0, {%1,%2};" : "=l"(r) : "f"(f.x), "f"(f.y)); return r;
}
__device__ __forceinline__ void unpack2(ull v, float& lo, float& hi) {
    asm("mov.b64 {%0,%1}, %2;" : "=f"(lo), "=f"(hi) : "l"(v));
}
__device__ __forceinline__ void fma2(ull& d, ull a, ull b) {
    asm("fma.rn.f32x2 %0, %1, %2, %0;" : "+l"(d) : "l"(a), "l"(b));
}
__device__ __forceinline__ ull add2(ull a, ull b) {
    ull r; asm("add.rn.f32x2 %0, %1, %2;" : "=l"(r) : "l"(a), "l"(b)); return r;
}
__device__ __forceinline__ ull h2tof2(unsigned int h) {
    __half2 hv = *reinterpret_cast<__half2*>(&h);
    float2 f = __half22float2(hv);
    return packf2(f);
}
__device__ __forceinline__ float2 h2f2(unsigned int h) {
    __half2 hv = *reinterpret_cast<__half2*>(&h);
    return __half22float2(hv);
}
__device__ __forceinline__ unsigned int f2h2(float lo, float hi) {
    __half2 p = __floats2half2_rn(lo, hi);
    return *(unsigned int*)&p;
}

__global__ void k_zero() {
    int i = blockIdx.x * blockDim.x + threadIdx.x;
    if (i < N_NODES) g_degi[i] = 0;
}

__global__ void k_count(const int* __restrict__ dst) {
    int e = blockIdx.x * blockDim.x + threadIdx.x;
    if (e < N_EDGES) atomicAdd(&g_degi[dst[e]], 1);
}

// ---- exclusive prefix scan over g_degi (50000) -> g_off ----
__global__ void k_scan1() {
    int tid = threadIdx.x;
    int i = blockIdx.x * 1024 + tid;
    int v = (i < N_NODES) ? g_degi[i] : 0;
    int lane = tid & 31, wid = tid >> 5;
    int s = v;
#pragma unroll
    for (int o = 1; o < 32; o <<= 1) {
        int t = __shfl_up_sync(0xffffffffu, s, o);
        if (lane >= o) s += t;
    }
    __shared__ int ws[32];
    if (lane == 31) ws[wid] = s;
    __syncthreads();
    if (wid == 0) {
        int t = ws[lane];
        int ss = t;
#pragma unroll
        for (int o = 1; o < 32; o <<= 1) {
            int u = __shfl_up_sync(0xffffffffu, ss, o);
            if (lane >= o) ss += u;
        }
        ws[lane] = ss - t;
    }
    __syncthreads();
    int excl = ws[wid] + s - v;
    if (i < N_NODES) g_off[i] = excl;
    if (tid == 1023) g_bsum[blockIdx.x] = ws[31] + s;
}

// scan3: per-block base via redundant smem sum; init cursor; dinv (incl. self loop)
__global__ void k_scan3(int nb) {
    __shared__ int sb[64];
    __shared__ int base_s;
    int tid = threadIdx.x;
    if (tid < 64) sb[tid] = (tid < nb) ? g_bsum[tid] : 0;
    __syncthreads();
    if (tid == 0) {
        int b = 0;
        for (int j = 0; j < (int)blockIdx.x; j++) b += sb[j];
        base_s = b;
    }
    __syncthreads();
    int i = blockIdx.x * 1024 + tid;
    if (i >= N_NODES) return;
    int o = g_off[i] + base_s;
    g_off[i] = o;
    g_cursor[i] = o;
    g_dinv[i] = rsqrtf((float)(g_degi[i] + 1));
}

// CSR fill: store src id directly
__global__ void k_fill(const int* __restrict__ src, const int* __restrict__ dst) {
    int e = blockIdx.x * blockDim.x + threadIdx.x;
    if (e >= N_EDGES) return;
    int pos = atomicAdd(&g_cursor[dst[e]], 1);
    g_esrc[pos] = src[e];
}

// t = x @ W1 (fp16 out) — row-major tiles, float4 fills, 4-k chunked inner loop.
// block 256, 64x64 tile, thread = 4 rows x 4 cols
__global__ void k_mm1(const float* __restrict__ x, const float* __restrict__ W1) {
    __shared__ float sW[64 * 64];        // [k][j]
    __shared__ float sx[64 * 68];        // row-major [r][k], pitch 68 floats (17 float4)
    int tid = threadIdx.x;
    int row0 = blockIdx.x * 64;
    const float4* W4 = (const float4*)W1;
    float4* sW4s = (float4*)sW;
    for (int i = tid; i < 1024; i += 256) sW4s[i] = W4[i];
    const float4* x4 = (const float4*)x;
    float4* sx4 = (float4*)sx;
    for (int i = tid; i < 1024; i += 256) {
        int r = i >> 4, q = i & 15;
        int row = row0 + r;
        float4 v = (row < N_NODES) ? x4[row * 16 + q] : make_float4(0.f, 0.f, 0.f, 0.f);
        sx4[r * 17 + q] = v;
    }
    __syncthreads();
    int ty = tid >> 4, tx = tid & 15;
    ull c0a = 0, c0b = 0, c1a = 0, c1b = 0, c2a = 0, c2b = 0, c3a = 0, c3b = 0;
    const ulonglong2* sWu = (const ulonglong2*)sW;
    int rb = ty * 4;
#pragma unroll
    for (int k4 = 0; k4 < 16; k4++) {
        float4 xv0 = *(const float4*)&sx[(rb + 0) * 68 + k4 * 4];
        float4 xv1 = *(const float4*)&sx[(rb + 1) * 68 + k4 * 4];
        float4 xv2 = *(const float4*)&sx[(rb + 2) * 68 + k4 * 4];
        float4 xv3 = *(const float4*)&sx[(rb + 3) * 68 + k4 * 4];
        const float* p0 = &xv0.x;
        const float* p1 = &xv1.x;
        const float* p2 = &xv2.x;
        const float* p3 = &xv3.x;
#pragma unroll
        for (int j = 0; j < 4; j++) {
            int k = k4 * 4 + j;
            ulonglong2 w = sWu[k * 16 + tx];
            ull X0 = pack2(p0[j]), X1 = pack2(p1[j]), X2 = pack2(p2[j]), X3 = pack2(p3[j]);
            fma2(c0a, X0, w.x); fma2(c0b, X0, w.y);
            fma2(c1a, X1, w.x); fma2(c1b, X1, w.y);
            fma2(c2a, X2, w.x); fma2(c2b, X2, w.y);
            fma2(c3a, X3, w.x); fma2(c3b, X3, w.y);
        }
    }
    // fp16 epilogue: each thread owns 4 rows x 4 cols -> uint2 per row
    uint2* th2 = (uint2*)g_th;   // 16 uint2 per node row (64 halves)
    int row = row0 + rb;
    float lo, hi;
    uint2 u;
    unpack2(c0a, lo, hi); u.x = f2h2(lo, hi);
    unpack2(c0b, lo, hi); u.y = f2h2(lo, hi);
    if (row + 0 < N_NODES) th2[(row + 0) * 16 + tx] = u;
    unpack2(c1a, lo, hi); u.x = f2h2(lo, hi);
    unpack2(c1b, lo, hi); u.y = f2h2(lo, hi);
    if (row + 1 < N_NODES) th2[(row + 1) * 16 + tx] = u;
    unpack2(c2a, lo, hi); u.x = f2h2(lo, hi);
    unpack2(c2b, lo, hi); u.y = f2h2(lo, hi);
    if (row + 2 < N_NODES) th2[(row + 2) * 16 + tx] = u;
    unpack2(c3a, lo, hi); u.x = f2h2(lo, hi);
    unpack2(c3b, lo, hi); u.y = f2h2(lo, hi);
    if (row + 3 < N_NODES) th2[(row + 3) * 16 + tx] = u;
}

// CSR gather-reduce over fp16 t, no atomics. 16 threads/node, uint2 (4 cols) each.
__global__ void k_agg(const int* __restrict__ dummy) {
    unsigned int gid = blockIdx.x * blockDim.x + threadIdx.x;
    unsigned int n = gid >> 4;
    int c = gid & 15;
    if (n >= N_NODES) return;
    const uint2* t2 = (const uint2*)g_th;
    float dn = g_dinv[n];
    uint2 u = t2[n * 16 + c];
    float2 s01 = h2f2(u.x), s23 = h2f2(u.y);
    float w2 = dn * dn;
    float4 acc = make_float4(s01.x * w2, s01.y * w2, s23.x * w2, s23.y * w2);
    int beg = g_off[n];
    int end = beg + g_degi[n];
#pragma unroll 4
    for (int j = beg; j < end; j++) {
        int s = g_esrc[j];             // broadcast across the 16-thread group
        float w = dn * g_dinv[s];
        uint2 uu = t2[s * 16 + c];
        float2 a01 = h2f2(uu.x), a23 = h2f2(uu.y);
        acc.x += a01.x * w; acc.y += a01.y * w;
        acc.z += a23.x * w; acc.w += a23.y * w;
    }
    ((float4*)g_agg)[n * 16 + c] = acc;
}

// h = relu(agg + b1); P = [h@Wm1[0:64]+bm1 | h@Wm1[64:128]] stored fp16
// row-major h tile, float4 fills, 4-k chunked inner loop.
__global__ void k_mm2(const float* __restrict__ Wm1, const float* __restrict__ b1,
                      const float* __restrict__ bm1) {
    __shared__ float sW[64 * 128];  // [k][0:64]=Wm1[k], [k][64:128]=Wm1[64+k]
    __shared__ float sh[64 * 68];   // row-major [r][k], pitch 68
    int tid = threadIdx.x;
    int row0 = blockIdx.x * 64;
    const float4* Wm14 = (const float4*)Wm1;
    float4* sW4s = (float4*)sW;
    for (int i = tid; i < 2048; i += 256) {
        int k = i >> 5, jq = i & 31;
        float4 v = (jq < 16) ? Wm14[k * 16 + jq] : Wm14[(64 + k) * 16 + (jq - 16)];
        sW4s[i] = v;
    }
    const float4* agg4 = (const float4*)g_agg;
    const float4* b14 = (const float4*)b1;
    float4* sh4 = (float4*)sh;
    for (int i = tid; i < 1024; i += 256) {
        int r = i >> 4, q = i & 15;
        int row = row0 + r;
        float4 v = make_float4(0.f, 0.f, 0.f, 0.f);
        if (row < N_NODES) {
            float4 a = agg4[row * 16 + q];
            float4 b = b14[q];
            v.x = fmaxf(a.x + b.x, 0.f); v.y = fmaxf(a.y + b.y, 0.f);
            v.z = fmaxf(a.z + b.z, 0.f); v.w = fmaxf(a.w + b.w, 0.f);
        }
        sh4[r * 17 + q] = v;
    }
    __syncthreads();
    int ty = tid >> 4, tx = tid & 15;
    ull a0[4] = {0,0,0,0}, a1[4] = {0,0,0,0}, a2[4] = {0,0,0,0}, a3[4] = {0,0,0,0};
    const ulonglong2* sWu = (const ulonglong2*)sW;
    int rb = ty * 4;
#pragma unroll
    for (int k4 = 0; k4 < 16; k4++) {
        float4 hv0 = *(const float4*)&sh[(rb + 0) * 68 + k4 * 4];
        float4 hv1 = *(const float4*)&sh[(rb + 1) * 68 + k4 * 4];
        float4 hv2 = *(const float4*)&sh[(rb + 2) * 68 + k4 * 4];
        float4 hv3 = *(const float4*)&sh[(rb + 3) * 68 + k4 * 4];
        const float* p0 = &hv0.x;
        const float* p1 = &hv1.x;
        const float* p2 = &hv2.x;
        const float* p3 = &hv3.x;
#pragma unroll
        for (int j = 0; j < 4; j++) {
            int k = k4 * 4 + j;
            ulonglong2 wa = sWu[k * 32 + tx * 2 + 0];
            ulonglong2 wb = sWu[k * 32 + tx * 2 + 1];
            ull H0 = pack2(p0[j]), H1 = pack2(p1[j]), H2 = pack2(p2[j]), H3 = pack2(p3[j]);
            fma2(a0[0], H0, wa.x); fma2(a0[1], H0, wa.y); fma2(a0[2], H0, wb.x); fma2(a0[3], H0, wb.y);
            fma2(a1[0], H1, wa.x); fma2(a1[1], H1, wa.y); fma2(a1[2], H1, wb.x); fma2(a1[3], H1, wb.y);
            fma2(a2[0], H2, wa.x); fma2(a2[1], H2, wa.y); fma2(a2[2], H2, wb.x); fma2(a2[3], H2, wb.y);
            fma2(a3[0], H3, wa.x); fma2(a3[1], H3, wa.y); fma2(a3[2], H3, wb.x); fma2(a3[3], H3, wb.y);
        }
    }
    if (tx < 8) {  // fold bm1 into A half (added exactly once per edge)
        const ulonglong2* bmu = (const ulonglong2*)bm1;
        ulonglong2 ba = bmu[tx * 2 + 0];
        ulonglong2 bb = bmu[tx * 2 + 1];
        a0[0] = add2(a0[0], ba.x); a0[1] = add2(a0[1], ba.y); a0[2] = add2(a0[2], bb.x); a0[3] = add2(a0[3], bb.y);
        a1[0] = add2(a1[0], ba.x); a1[1] = add2(a1[1], ba.y); a1[2] = add2(a1[2], bb.x); a1[3] = add2(a1[3], bb.y);
        a2[0] = add2(a2[0], ba.x); a2[1] = add2(a2[1], ba.y); a2[2] = add2(a2[2], bb.x); a2[3] = add2(a2[3], bb.y);
        a3[0] = add2(a3[0], ba.x); a3[1] = add2(a3[1], ba.y); a3[2] = add2(a3[2], bb.x); a3[3] = add2(a3[3], bb.y);
    }
    uint4* P4 = (uint4*)g_Ph;
    int row = row0 + rb;
    ull* rows[4] = {a0, a1, a2, a3};
#pragma unroll
    for (int rr = 0; rr < 4; rr++) {
        if (row + rr >= N_NODES) break;
        float lo, hi;
        uint4 u;
        unpack2(rows[rr][0], lo, hi); u.x = f2h2(lo, hi);
        unpack2(rows[rr][1], lo, hi); u.y = f2h2(lo, hi);
        unpack2(rows[rr][2], lo, hi); u.z = f2h2(lo, hi);
        unpack2(rows[rr][3], lo, hi); u.w = f2h2(lo, hi);
        P4[(row + rr) * 16 + tx] = u;   // 8 cols starting at 8*tx
    }
}

// per-edge: hidden = relu(A[src] + B[dst] + ea@We); out = sigmoid(hidden . Wm2 + bm2)
__global__ void k_edge(const int* __restrict__ src, const int* __restrict__ dst,
                       const float* __restrict__ ea, const float* __restrict__ Wm1,
                       const float* __restrict__ Wm2, const float* __restrict__ bm2,
                       float* __restrict__ out) {
    __shared__ ull sWe[16 * 32];  // Wm1 rows 128..143: [k][col-pair j2]
    __shared__ float sW2[64];
    __shared__ float sb2;
    int tid = threadIdx.x;
    for (int i = tid; i < 512; i += 256) {
        int k = i >> 5, j2 = i & 31;
        const float2* wrow = (const float2*)(Wm1 + (128 + k) * 64);
        sWe[i] = packf2(wrow[j2]);
    }
    if (tid < 64) sW2[tid] = Wm2[tid];
    if (tid == 0) sb2 = bm2[0];
    __syncthreads();
    unsigned int e = blockIdx.x * blockDim.x + tid;
    if (e >= N_EDGES) return;
    int s = src[e], d = dst[e];
    const uint4* PsA = (const uint4*)(g_Ph + s * 128);        // A half: 8 uint4
    const uint4* PdB = (const uint4*)(g_Ph + d * 128 + 64);   // B half: 8 uint4
    ull ek2[16];
    {
        const float4* ea4 = (const float4*)(ea + (size_t)e * 16);
#pragma unroll
        for (int q = 0; q < 4; q++) {
            float4 v = ea4[q];
            ek2[4 * q + 0] = pack2(v.x); ek2[4 * q + 1] = pack2(v.y);
            ek2[4 * q + 2] = pack2(v.z); ek2[4 * q + 3] = pack2(v.w);
        }
    }
    float acc = 0.f;
#pragma unroll
    for (int jg8 = 0; jg8 < 8; jg8++) {   // 8 cols per iteration
        uint4 au = PsA[jg8];
        uint4 bu = PdB[jg8];
        ull v0 = add2(h2tof2(au.x), h2tof2(bu.x));
        ull v1 = add2(h2tof2(au.y), h2tof2(bu.y));
        ull v2 = add2(h2tof2(au.z), h2tof2(bu.z));
        ull v3 = add2(h2tof2(au.w), h2tof2(bu.w));
#pragma unroll
        for (int k = 0; k < 16; k++) {
            const ull* w = &sWe[k * 32 + jg8 * 4];
            fma2(v0, ek2[k], w[0]);
            fma2(v1, ek2[k], w[1]);
            fma2(v2, ek2[k], w[2]);
            fma2(v3, ek2[k], w[3]);
        }
        float f0, f1, f2, f3, f4, f5, f6, f7;
        unpack2(v0, f0, f1); unpack2(v1, f2, f3);
        unpack2(v2, f4, f5); unpack2(v3, f6, f7);
        f0 = fmaxf(f0, 0.f); f1 = fmaxf(f1, 0.f); f2 = fmaxf(f2, 0.f); f3 = fmaxf(f3, 0.f);
        f4 = fmaxf(f4, 0.f); f5 = fmaxf(f5, 0.f); f6 = fmaxf(f6, 0.f); f7 = fmaxf(f7, 0.f);
        const float* w2 = &sW2[jg8 * 8];
        acc += f0 * w2[0] + f1 * w2[1] + f2 * w2[2] + f3 * w2[3]
             + f4 * w2[4] + f5 * w2[5] + f6 * w2[6] + f7 * w2[7];
    }
    out[e] = 1.f / (1.f + __expf(-(acc + sb2)));
}

extern "C" void kernel_launch(void* const* d_in, const int* in_sizes, int n_in,
                              void* d_out, int out_size) {
    const float* x   = (const float*)d_in[0];
    const int*   src = (const int*)d_in[1];
    const int*   dst = (const int*)d_in[2];
    const float* ea  = (const float*)d_in[3];
    const float* W1  = (const float*)d_in[4];
    const float* b1  = (const float*)d_in[5];
    const float* Wm1 = (const float*)d_in[6];
    const float* bm1 = (const float*)d_in[7];
    const float* Wm2 = (const float*)d_in[8];
    const float* bm2 = (const float*)d_in[9];
    float* out = (float*)d_out;
    (void)in_sizes; (void)n_in; (void)out_size;

    const int NB_SCAN = (N_NODES + 1023) / 1024;  // 49

    k_zero<<<(N_NODES + 255) / 256, 256>>>();
    k_count<<<(N_EDGES + 255) / 256, 256>>>(dst);
    k_scan1<<<NB_SCAN, 1024>>>();
    k_mm1<<<(N_NODES + 63) / 64, 256>>>(x, W1);   // launch #4 → ncu capture slot
    k_scan3<<<NB_SCAN, 1024>>>(NB_SCAN);
    k_fill<<<(N_EDGES + 255) / 256, 256>>>(src, dst);
    k_agg<<<(N_NODES * 16 + 255) / 256, 256>>>(src);
    k_mm2<<<(N_NODES + 63) / 64, 256>>>(Wm1, b1, bm1);
    k_edge<<<(N_EDGES + 255) / 256, 256>>>(src, dst, ea, Wm1, Wm2, bm2, out);
}